// round 5
// baseline (speedup 1.0000x reference)
#include <cuda_runtime.h>

// Problem constants
#define BB 4
#define LL 512
#define VV 4
#define DD 256
#define DS 16
#define DI 512
#define DCONV 4
#define DTR 16

static constexpr int M_ROWS = BB * LL;                         // 2048 rows/view
static constexpr size_t OUT_ONE = (size_t)BB * LL * VV * DD;   // 2,097,152

// -------- scratch (static device globals; no allocation allowed) ----------
__device__ __align__(16) float g_xn   [(size_t)VV * M_ROWS * DD];       //  8 MB
__device__ __align__(16) float g_xz   [(size_t)VV * M_ROWS * 2 * DI];   // 32 MB (xi|z)
__device__ __align__(16) float g_xc   [(size_t)VV * M_ROWS * DI];       // 16 MB
__device__ __align__(16) float g_xdbl [(size_t)VV * M_ROWS * 48];       // 1.5 MB (dt|B|C)
__device__ __align__(16) float g_delta[(size_t)VV * M_ROWS * DI];       // 16 MB
__device__ __align__(16) float g_y    [(size_t)VV * M_ROWS * DI];       // 16 MB

// -------- packed f32x2 helpers --------------------------------------------
__device__ __forceinline__ unsigned long long pk2(float x, float y) {
    unsigned long long r;
    asm("mov.b64 %0, {%1, %2};" : "=l"(r) : "f"(x), "f"(y));
    return r;
}
__device__ __forceinline__ unsigned long long ffma2(unsigned long long a,
                                                    unsigned long long b,
                                                    unsigned long long c) {
    unsigned long long d;
    asm("fma.rn.f32x2 %0, %1, %2, %3;" : "=l"(d) : "l"(a), "l"(b), "l"(c));
    return d;
}
__device__ __forceinline__ float2 upk2(unsigned long long v) {
    float2 r;
    asm("mov.b64 {%0, %1}, %2;" : "=f"(r.x), "=f"(r.y) : "l"(v));
    return r;
}
__device__ __forceinline__ float silu_f(float x) {
    return x / (1.0f + __expf(-x));
}

// ============================================================================
// Kernel 1: LayerNorm  x(B,L,V,D) -> g_xn (V, B*L, D)
// ============================================================================
__global__ __launch_bounds__(256)
void ln_kernel(const float* __restrict__ x,
               const float* __restrict__ gamma,
               const float* __restrict__ beta)
{
    const int row = blockIdx.x;
    const int v   = blockIdx.y;
    const int d   = threadIdx.x;

    float val = x[((size_t)row * VV + v) * DD + d];

    float s = val, q = val * val;
    #pragma unroll
    for (int o = 16; o; o >>= 1) {
        s += __shfl_xor_sync(0xffffffffu, s, o);
        q += __shfl_xor_sync(0xffffffffu, q, o);
    }
    __shared__ float sh[16];
    const int w = d >> 5, ln = d & 31;
    if (ln == 0) { sh[w] = s; sh[w + 8] = q; }
    __syncthreads();
    if (d == 0) {
        float S = 0.f, Q = 0.f;
        #pragma unroll
        for (int i = 0; i < 8; i++) { S += sh[i]; Q += sh[i + 8]; }
        const float mu  = S * (1.0f / DD);
        const float var = Q * (1.0f / DD) - mu * mu;
        sh[0] = mu;
        sh[1] = rsqrtf(var + 1e-5f);
    }
    __syncthreads();
    const float mu = sh[0], rs = sh[1];
    g_xn[((size_t)v * M_ROWS + row) * DD + d] =
        (val - mu) * rs * gamma[v * DD + d] + beta[v * DD + d];
}

// ============================================================================
// Kernels 2/7: big NT GEMM, 128x128 tile, double-buffered, f32x2 inner loop
//   MODE 0: g_xn @ w_in^T  -> g_xz   (M=2048, N=1024, K=256)
//   MODE 2: g_y  @ w_out^T -> d_out  (M=2048, N=256,  K=512) scatter + dup
// ============================================================================
template<int MODE>
__global__ __launch_bounds__(256, 2)
void gemm_big(const float* __restrict__ Wg, float* __restrict__ Cout, size_t dupOfs)
{
    constexpr int N = (MODE == 0) ? 1024 : 256;
    constexpr int K = (MODE == 0) ? 256 : 512;
    constexpr int KT = K / 16;

    const int v = blockIdx.z;
    const float* A = (MODE == 0 ? g_xn : g_y) + (size_t)v * M_ROWS * K;
    const float* W = Wg + (size_t)v * N * K;

    const int m0 = blockIdx.y * 128;
    const int n0 = blockIdx.x * 128;

    // A duplicated as (a,a) f32x2 pairs; W plain floats.
    __shared__ __align__(16) unsigned long long Asd[2][16][128];  // 32 KB
    __shared__ __align__(16) float              Ws [2][16][128];  // 16 KB

    const int tid = threadIdx.x;
    const int tm8 = (tid >> 4) * 8;       // 8 rows
    const int tn4 = (tid & 15) * 4;       // cols {tn4..+3, tn4+64..+67}

    unsigned long long acc[8][4];
    #pragma unroll
    for (int i = 0; i < 8; i++)
        #pragma unroll
        for (int p = 0; p < 4; p++) acc[i][p] = 0ull;

    const int lrow = tid >> 1;            // 0..127
    const int lk8  = (tid & 1) * 8;       // 0 or 8

    const float* Ap = A + (size_t)(m0 + lrow) * K + lk8;
    const float* Wp = W + (size_t)(n0 + lrow) * K + lk8;

    float4 pa0, pa1, pw0, pw1;

    auto ldg_tile = [&](int kk) {
        pa0 = *reinterpret_cast<const float4*>(Ap + kk);
        pa1 = *reinterpret_cast<const float4*>(Ap + kk + 4);
        pw0 = *reinterpret_cast<const float4*>(Wp + kk);
        pw1 = *reinterpret_cast<const float4*>(Wp + kk + 4);
    };
    auto sts_tile = [&](int buf) {
        Asd[buf][lk8 + 0][lrow] = pk2(pa0.x, pa0.x);
        Asd[buf][lk8 + 1][lrow] = pk2(pa0.y, pa0.y);
        Asd[buf][lk8 + 2][lrow] = pk2(pa0.z, pa0.z);
        Asd[buf][lk8 + 3][lrow] = pk2(pa0.w, pa0.w);
        Asd[buf][lk8 + 4][lrow] = pk2(pa1.x, pa1.x);
        Asd[buf][lk8 + 5][lrow] = pk2(pa1.y, pa1.y);
        Asd[buf][lk8 + 6][lrow] = pk2(pa1.z, pa1.z);
        Asd[buf][lk8 + 7][lrow] = pk2(pa1.w, pa1.w);
        Ws[buf][lk8 + 0][lrow] = pw0.x;
        Ws[buf][lk8 + 1][lrow] = pw0.y;
        Ws[buf][lk8 + 2][lrow] = pw0.z;
        Ws[buf][lk8 + 3][lrow] = pw0.w;
        Ws[buf][lk8 + 4][lrow] = pw1.x;
        Ws[buf][lk8 + 5][lrow] = pw1.y;
        Ws[buf][lk8 + 6][lrow] = pw1.z;
        Ws[buf][lk8 + 7][lrow] = pw1.w;
    };

    ldg_tile(0);
    sts_tile(0);
    __syncthreads();

    int buf = 0;
    for (int t = 0; t < KT; ++t) {
        if (t + 1 < KT) ldg_tile((t + 1) * 16);

        #pragma unroll
        for (int k = 0; k < 16; k++) {
            const ulonglong2 a01 = *reinterpret_cast<const ulonglong2*>(&Asd[buf][k][tm8]);
            const ulonglong2 a23 = *reinterpret_cast<const ulonglong2*>(&Asd[buf][k][tm8 + 2]);
            const ulonglong2 a45 = *reinterpret_cast<const ulonglong2*>(&Asd[buf][k][tm8 + 4]);
            const ulonglong2 a67 = *reinterpret_cast<const ulonglong2*>(&Asd[buf][k][tm8 + 6]);
            const ulonglong2 w0  = *reinterpret_cast<const ulonglong2*>(&Ws[buf][k][tn4]);
            const ulonglong2 w1  = *reinterpret_cast<const ulonglong2*>(&Ws[buf][k][tn4 + 64]);
            const unsigned long long av[8] =
                {a01.x, a01.y, a23.x, a23.y, a45.x, a45.y, a67.x, a67.y};
            #pragma unroll
            for (int i = 0; i < 8; i++) {
                acc[i][0] = ffma2(av[i], w0.x, acc[i][0]);
                acc[i][1] = ffma2(av[i], w0.y, acc[i][1]);
                acc[i][2] = ffma2(av[i], w1.x, acc[i][2]);
                acc[i][3] = ffma2(av[i], w1.y, acc[i][3]);
            }
        }

        if (t + 1 < KT) sts_tile(buf ^ 1);
        __syncthreads();
        buf ^= 1;
    }

    // epilogue: two float4 stores per row (cols tn4.., tn4+64..)
    #pragma unroll
    for (int i = 0; i < 8; i++) {
        const int row = m0 + tm8 + i;
        const float2 r00 = upk2(acc[i][0]), r01 = upk2(acc[i][1]);
        const float2 r10 = upk2(acc[i][2]), r11 = upk2(acc[i][3]);
        const float4 o0 = make_float4(r00.x, r00.y, r01.x, r01.y);
        const float4 o1 = make_float4(r10.x, r10.y, r11.x, r11.y);
        if (MODE == 0) {
            float* base = g_xz + ((size_t)v * M_ROWS + row) * N + n0;
            *reinterpret_cast<float4*>(base + tn4)      = o0;
            *reinterpret_cast<float4*>(base + tn4 + 64) = o1;
        } else {
            const size_t o = ((size_t)row * VV + v) * DD + n0;
            *reinterpret_cast<float4*>(Cout + o + tn4)                = o0;
            *reinterpret_cast<float4*>(Cout + o + tn4 + 64)           = o1;
            *reinterpret_cast<float4*>(Cout + dupOfs + o + tn4)       = o0;
            *reinterpret_cast<float4*>(Cout + dupOfs + o + tn4 + 64)  = o1;
        }
    }
}

// ============================================================================
// Kernel 3: depthwise causal conv (k=4) + bias + silu :  g_xz[:, :DI] -> g_xc
// ============================================================================
__global__ __launch_bounds__(256)
void conv_silu_kernel(const float* __restrict__ cw, const float* __restrict__ cb)
{
    const int idx = blockIdx.x * 256 + threadIdx.x;
    const int d4 = idx & 127;
    const int l  = (idx >> 7) & (LL - 1);
    const int bv = idx >> 16;
    const int v  = bv >> 2;

    const float* cwp = cw + ((size_t)v * DI + d4 * 4) * DCONV;
    const float4 c0 = *reinterpret_cast<const float4*>(cwp);
    const float4 c1 = *reinterpret_cast<const float4*>(cwp + 4);
    const float4 c2 = *reinterpret_cast<const float4*>(cwp + 8);
    const float4 c3 = *reinterpret_cast<const float4*>(cwp + 12);
    const float cwa0[4] = {c0.x, c0.y, c0.z, c0.w};
    const float cwa1[4] = {c1.x, c1.y, c1.z, c1.w};
    const float cwa2[4] = {c2.x, c2.y, c2.z, c2.w};
    const float cwa3[4] = {c3.x, c3.y, c3.z, c3.w};

    float4 acc = *reinterpret_cast<const float4*>(cb + (size_t)v * DI + d4 * 4);

    const float* xiBase = g_xz + (size_t)bv * LL * (2 * DI) + d4 * 4;
    #pragma unroll
    for (int k = 0; k < DCONV; k++) {
        const int lp = l - (DCONV - 1) + k;
        if (lp >= 0) {
            const float4 xi = *reinterpret_cast<const float4*>(
                xiBase + (size_t)lp * (2 * DI));
            acc.x = fmaf(cwa0[k], xi.x, acc.x);
            acc.y = fmaf(cwa1[k], xi.y, acc.y);
            acc.z = fmaf(cwa2[k], xi.z, acc.z);
            acc.w = fmaf(cwa3[k], xi.w, acc.w);
        }
    }
    acc.x = silu_f(acc.x);
    acc.y = silu_f(acc.y);
    acc.z = silu_f(acc.z);
    acc.w = silu_f(acc.w);
    *reinterpret_cast<float4*>(
        g_xc + ((size_t)bv * LL + l) * DI + d4 * 4) = acc;
}

// ============================================================================
// Kernel 4: small GEMM  g_xc @ w_x^T -> g_xdbl  (M=2048, N=48, K=512)
//   32-row tiles, K packed into f32x2 pairs, padded smem (conflict-free).
// ============================================================================
__global__ __launch_bounds__(256)
void gemm_small(const float* __restrict__ Wg)
{
    constexpr int K = 512;
    const int v  = blockIdx.y;
    const int m0 = blockIdx.x * 32;

    const float* A = g_xc + (size_t)v * M_ROWS * K;
    const float* W = Wg + (size_t)v * 48 * K;

    __shared__ __align__(16) float As[32][36];   // [m][k] padded
    __shared__ __align__(16) float Ws[48][36];   // [n][k] padded

    const int tid = threadIdx.x;
    const int tm = tid >> 4;      // rows tm*2, tm*2+1
    const int tn = tid & 15;      // cols tn*3..tn*3+2

    unsigned long long acc[2][3];
    #pragma unroll
    for (int r = 0; r < 2; r++)
        #pragma unroll
        for (int c = 0; c < 3; c++) acc[r][c] = 0ull;

    const int ar  = tid & 31;            // A loader row
    const int ak4 = (tid >> 5) * 4;      // A loader k-offset
    const int wk  = tid & 31;            // W loader k
    const int wn0 = tid >> 5;            // W loader n base

    for (int kk = 0; kk < K; kk += 32) {
        // A tile 32x32
        {
            const float4 va = *reinterpret_cast<const float4*>(
                A + (size_t)(m0 + ar) * K + kk + ak4);
            *reinterpret_cast<float4*>(&As[ar][ak4]) = va;
        }
        // W tile 48x32
        #pragma unroll
        for (int r = 0; r < 6; r++) {
            const int n = wn0 + 8 * r;
            Ws[n][wk] = W[(size_t)n * K + kk + wk];
        }
        __syncthreads();

        #pragma unroll
        for (int kp = 0; kp < 16; kp++) {
            const unsigned long long a0 =
                *reinterpret_cast<const unsigned long long*>(&As[tm * 2][kp * 2]);
            const unsigned long long a1 =
                *reinterpret_cast<const unsigned long long*>(&As[tm * 2 + 1][kp * 2]);
            #pragma unroll
            for (int c = 0; c < 3; c++) {
                const unsigned long long w =
                    *reinterpret_cast<const unsigned long long*>(&Ws[tn * 3 + c][kp * 2]);
                acc[0][c] = ffma2(a0, w, acc[0][c]);
                acc[1][c] = ffma2(a1, w, acc[1][c]);
            }
        }
        __syncthreads();
    }

    #pragma unroll
    for (int r = 0; r < 2; r++) {
        const int row = m0 + tm * 2 + r;
        #pragma unroll
        for (int c = 0; c < 3; c++) {
            const float2 u = upk2(acc[r][c]);
            g_xdbl[((size_t)v * M_ROWS + row) * 48 + tn * 3 + c] = u.x + u.y;
        }
    }
}

// ============================================================================
// Kernel 5: delta precompute (pulled off the scan's serial critical path)
//   delta[v][row][d] = softplus( dot(xdbl_dt[row], w_dt[v][d]) + b_dt[v][d] )
// ============================================================================
__global__ __launch_bounds__(256)
void delta_kernel(const float* __restrict__ w_dt, const float* __restrict__ b_dt)
{
    const int rowblk = blockIdx.x;           // 64 blocks of 32 rows
    const int dh     = blockIdx.y;           // d-half
    const int v      = blockIdx.z;
    const int tid    = threadIdx.x;
    const int d      = dh * 256 + tid;
    const int r0     = rowblk * 32;

    __shared__ float sdt[32][16];
    #pragma unroll
    for (int i = tid; i < 512; i += 256) {
        const int row = i >> 4, c = i & 15;
        sdt[row][c] = g_xdbl[((size_t)v * M_ROWS + r0 + row) * 48 + c];
    }
    __syncthreads();

    float w[16];
    {
        const float* wp = w_dt + ((size_t)v * DI + d) * DTR;
        #pragma unroll
        for (int i = 0; i < 4; i++) {
            const float4 t = *reinterpret_cast<const float4*>(wp + i * 4);
            w[i * 4] = t.x; w[i * 4 + 1] = t.y; w[i * 4 + 2] = t.z; w[i * 4 + 3] = t.w;
        }
    }
    const float bd = b_dt[(size_t)v * DI + d];

    float* out = g_delta + ((size_t)v * M_ROWS + r0) * DI + d;
    #pragma unroll 4
    for (int row = 0; row < 32; row++) {
        float p = bd;
        #pragma unroll
        for (int c = 0; c < 16; c++) p = fmaf(sdt[row][c], w[c], p);
        const float delta = fmaxf(p, 0.f) + log1pf(__expf(-fabsf(p)));
        out[(size_t)row * DI] = delta;
    }
}

// ============================================================================
// Kernel 6: selective scan (delta precomputed; only exp+fma on the h-chain)
// ============================================================================
__global__ __launch_bounds__(256)
void scan_kernel(const float* __restrict__ A_log, const float* __restrict__ D_skip)
{
    const int gid = blockIdx.x * 32 + (threadIdx.x >> 3);   // v*B*DI groups
    const int j   = threadIdx.x & 7;
    const int d   = gid & (DI - 1);
    const int b   = (gid >> 9) & (BB - 1);
    const int v   = gid >> 11;
    const int n0  = j * 2;

    const float* alp = A_log + ((size_t)v * DI + d) * DS + n0;
    const float negA0 = -__expf(alp[0]);
    const float negA1 = -__expf(alp[1]);
    const float dsk = D_skip[(size_t)v * DI + d];

    const int bv = v * BB + b;
    const float* xdb  = g_xdbl  + (size_t)bv * LL * 48;
    const float* xcP  = g_xc    + (size_t)bv * LL * DI + d;
    const float* zP   = g_xz    + (size_t)bv * LL * (2 * DI) + DI + d;
    const float* dltP = g_delta + (size_t)bv * LL * DI + d;
    float*       yP   = g_y     + (size_t)bv * LL * DI + d;

    float h0 = 0.f, h1 = 0.f;

    #pragma unroll 4
    for (int l = 0; l < LL; l++) {
        const float* rp = xdb + l * 48;
        const float2 Bc = *reinterpret_cast<const float2*>(rp + 16 + n0);
        const float2 Cc = *reinterpret_cast<const float2*>(rp + 32 + n0);
        const float xc    = __ldg(xcP  + (size_t)l * DI);
        const float delta = __ldg(dltP + (size_t)l * DI);

        const float dxc = delta * xc;
        h0 = fmaf(__expf(delta * negA0), h0, dxc * Bc.x);
        h1 = fmaf(__expf(delta * negA1), h1, dxc * Bc.y);

        float t = fmaf(h1, Cc.y, h0 * Cc.x);
        t += __shfl_xor_sync(0xffffffffu, t, 4);
        t += __shfl_xor_sync(0xffffffffu, t, 2);
        t += __shfl_xor_sync(0xffffffffu, t, 1);

        if (j == 0) {
            const float z = zP[(size_t)l * (2 * DI)];
            yP[(size_t)l * DI] = fmaf(xc, dsk, t) * silu_f(z);
        }
    }
}

// ============================================================================
// launch
// ============================================================================
extern "C" void kernel_launch(void* const* d_in, const int* in_sizes, int n_in,
                              void* d_out, int out_size)
{
    const float* x      = (const float*)d_in[0];
    const float* ln_g   = (const float*)d_in[1];
    const float* ln_b   = (const float*)d_in[2];
    const float* w_in   = (const float*)d_in[3];
    const float* conv_w = (const float*)d_in[4];
    const float* conv_b = (const float*)d_in[5];
    const float* w_x    = (const float*)d_in[6];
    const float* w_dt   = (const float*)d_in[7];
    const float* b_dt   = (const float*)d_in[8];
    const float* A_log  = (const float*)d_in[9];
    const float* D_skip = (const float*)d_in[10];
    const float* w_out  = (const float*)d_in[11];
    float* out = (float*)d_out;

    const size_t dup = ((size_t)out_size >= 2 * OUT_ONE) ? OUT_ONE : 0;

    // 1) layernorm
    ln_kernel<<<dim3(M_ROWS, VV), 256>>>(x, ln_g, ln_b);

    // 2) xz = xn @ w_in^T   (128x128 tiles, 512 blocks)
    gemm_big<0><<<dim3(1024 / 128, M_ROWS / 128, VV), 256>>>(w_in, nullptr, 0);

    // 3) depthwise causal conv + silu -> xc
    conv_silu_kernel<<<(VV * BB * LL * (DI / 4)) / 256, 256>>>(conv_w, conv_b);

    // 4) xdbl = xc @ w_x^T  (32-row tiles, 256 blocks)
    gemm_small<<<dim3(M_ROWS / 32, VV), 256>>>(w_x);

    // 5) delta = softplus(dt @ w_dt^T + b_dt), off the scan critical path
    delta_kernel<<<dim3(M_ROWS / 32, 2, VV), 256>>>(w_dt, b_dt);

    // 6) selective scan + D-skip + silu(z) gating -> y
    scan_kernel<<<(VV * BB * DI) / 32, 256>>>(A_log, D_skip);

    // 7) out = y @ w_out^T scattered into (B,L,V,D), duplicated
    gemm_big<2><<<dim3(256 / 128, M_ROWS / 128, VV), 256>>>(w_out, out, dup);
}